// round 3
// baseline (speedup 1.0000x reference)
#include <cuda_runtime.h>

#define D      128
#define DO2    256          // 2*D_OUT
#define NODES  50000
#define TILE   32           // nodes per block in gemm_ln
#define LN_EPS 1e-5f

// Scratch (no cudaMalloc allowed)
__device__ float g_support[NODES * D];   // 25.6 MB
__device__ float g_Wt[D * DO2];          // Wt[k][c]

// ---------------------------------------------------------------------------
// Packed f32x2 helpers (sm_10x FFMA2 path — only reachable via PTX)
__device__ __forceinline__ unsigned long long pack2(float a) {
    unsigned long long r;
    asm("mov.b64 %0, {%1, %1};" : "=l"(r) : "f"(a));
    return r;
}
__device__ __forceinline__ void ffma2(unsigned long long& d,
                                      unsigned long long a,
                                      unsigned long long b) {
    asm("fma.rn.f32x2 %0, %1, %2, %0;" : "+l"(d) : "l"(a), "l"(b));
}

// ---------------------------------------------------------------------------
// Fused prep: zero the scatter accumulator + build transposed weight matrix.
__global__ void prep_kernel(const float* __restrict__ Ws,
                            const float* __restrict__ Wn) {
    int i = blockIdx.x * blockDim.x + threadIdx.x;
    const int n4 = NODES * D / 4;
    if (i < n4) {
        reinterpret_cast<float4*>(g_support)[i] = make_float4(0.f, 0.f, 0.f, 0.f);
    }
    if (i < D * DO2) {
        int k = i / DO2;
        int c = i % DO2;
        g_Wt[i] = (c < D) ? Ws[c * D + k] : Wn[(c - D) * D + k];
    }
}

// ---------------------------------------------------------------------------
// One warp per edge: lane l handles 4 consecutive features (float4).
__global__ void spmm_scatter_kernel(const float* __restrict__ h,
                                    const int*  __restrict__ row,
                                    const int*  __restrict__ col,
                                    const float* __restrict__ val,
                                    int E) {
    int gw   = (blockIdx.x * blockDim.x + threadIdx.x) >> 5;
    int lane = threadIdx.x & 31;
    if (gw >= E) return;
    int   r = __ldg(row + gw);
    int   c = __ldg(col + gw);
    float v = __ldg(val + gw);

    float4 x = reinterpret_cast<const float4*>(h + (size_t)c * D)[lane];
    x.x *= v; x.y *= v; x.z *= v; x.w *= v;

    float4* dst = reinterpret_cast<float4*>(g_support + (size_t)r * D) + lane;
    atomicAdd(dst, x);   // vector REDG.128
}

// ---------------------------------------------------------------------------
// Fused GEMM + concat + ReLU + LayerNorm with FFMA2 inner product.
// 256 threads, 32 nodes/block. cq = tid&63 (4 output channels = 2 f32x2
// pairs), ng = tid>>6 (8 nodes). acc[8 nodes][2 channel-pairs] in f32x2.
__global__ __launch_bounds__(256)
void gemm_ln_kernel(const float* __restrict__ h,
                    const float* __restrict__ b_self,
                    const float* __restrict__ b_neigh,
                    const float* __restrict__ gamma,
                    const float* __restrict__ beta,
                    float* __restrict__ out) {
    // 32 KB, reused: phase 1 = sH[32][128] + sS[32][128]; phase 2 = sOut[32][256]
    __shared__ float smem[TILE * DO2];
    float* sH = smem;
    float* sS = smem + TILE * D;

    const int tid   = threadIdx.x;
    const int node0 = blockIdx.x * TILE;

    // Load node tiles (coalesced float4), zero-pad past NODES
    for (int i = tid; i < TILE * (D / 4); i += 256) {
        int row   = i >> 5;           // D/4 = 32 float4 per row
        int gnode = node0 + row;
        float4 a = make_float4(0.f, 0.f, 0.f, 0.f);
        float4 s = a;
        if (gnode < NODES) {
            a = reinterpret_cast<const float4*>(h + (size_t)gnode * D)[i & 31];
            s = reinterpret_cast<const float4*>(g_support + (size_t)gnode * D)[i & 31];
        }
        reinterpret_cast<float4*>(sH)[i] = a;
        reinterpret_cast<float4*>(sS)[i] = s;
    }
    __syncthreads();

    const int  cq    = tid & 63;
    const int  ng    = tid >> 6;
    const int  n0    = ng * 8;
    const bool neigh = (cq >= 32);
    const float* sX  = neigh ? sS : sH;

    float4 bias = neigh ? reinterpret_cast<const float4*>(b_neigh)[cq - 32]
                        : reinterpret_cast<const float4*>(b_self)[cq];

    unsigned long long acc[8][2];
    {
        unsigned long long b01, b23;
        asm("mov.b64 %0, {%1, %2};" : "=l"(b01) : "f"(bias.x), "f"(bias.y));
        asm("mov.b64 %0, {%1, %2};" : "=l"(b23) : "f"(bias.z), "f"(bias.w));
        #pragma unroll
        for (int j = 0; j < 8; j++) { acc[j][0] = b01; acc[j][1] = b23; }
    }

    const float4* Wt4 = reinterpret_cast<const float4*>(g_Wt); // [k][64]
    #pragma unroll 2
    for (int k = 0; k < D; k += 4) {
        float4 w0 = __ldg(Wt4 + (k + 0) * 64 + cq);
        float4 w1 = __ldg(Wt4 + (k + 1) * 64 + cq);
        float4 w2 = __ldg(Wt4 + (k + 2) * 64 + cq);
        float4 w3 = __ldg(Wt4 + (k + 3) * 64 + cq);
        const unsigned long long* w0p = reinterpret_cast<const unsigned long long*>(&w0);
        const unsigned long long* w1p = reinterpret_cast<const unsigned long long*>(&w1);
        const unsigned long long* w2p = reinterpret_cast<const unsigned long long*>(&w2);
        const unsigned long long* w3p = reinterpret_cast<const unsigned long long*>(&w3);
        #pragma unroll
        for (int j = 0; j < 8; j++) {
            float4 xv = *reinterpret_cast<const float4*>(sX + (n0 + j) * D + k);
            unsigned long long xx;
            xx = pack2(xv.x);
            ffma2(acc[j][0], w0p[0], xx);
            ffma2(acc[j][1], w0p[1], xx);
            xx = pack2(xv.y);
            ffma2(acc[j][0], w1p[0], xx);
            ffma2(acc[j][1], w1p[1], xx);
            xx = pack2(xv.z);
            ffma2(acc[j][0], w2p[0], xx);
            ffma2(acc[j][1], w2p[1], xx);
            xx = pack2(xv.w);
            ffma2(acc[j][0], w3p[0], xx);
            ffma2(acc[j][1], w3p[1], xx);
        }
    }
    __syncthreads();   // all sX reads done; smem is now free to reuse

    // ReLU + stage into shared as sOut[32][256]
    #pragma unroll
    for (int j = 0; j < 8; j++) {
        const float2 a01 = *reinterpret_cast<const float2*>(&acc[j][0]);
        const float2 a23 = *reinterpret_cast<const float2*>(&acc[j][1]);
        float4 r;
        r.x = fmaxf(a01.x, 0.f);
        r.y = fmaxf(a01.y, 0.f);
        r.z = fmaxf(a23.x, 0.f);
        r.w = fmaxf(a23.y, 0.f);
        reinterpret_cast<float4*>(smem)[(n0 + j) * 64 + cq] = r;
    }
    __syncthreads();

    // LayerNorm: 8 warps, 4 rows each; lane handles 8 values (2 float4)
    const int wid  = tid >> 5;
    const int lane = tid & 31;

    float4 g1 = __ldg(reinterpret_cast<const float4*>(gamma) + lane);
    float4 g2 = __ldg(reinterpret_cast<const float4*>(gamma) + lane + 32);
    float4 e1 = __ldg(reinterpret_cast<const float4*>(beta)  + lane);
    float4 e2 = __ldg(reinterpret_cast<const float4*>(beta)  + lane + 32);

    #pragma unroll
    for (int rr = 0; rr < 4; rr++) {
        int n = wid * 4 + rr;
        float4 a = reinterpret_cast<float4*>(smem)[n * 64 + lane];
        float4 b = reinterpret_cast<float4*>(smem)[n * 64 + lane + 32];
        float s  = a.x + a.y + a.z + a.w + b.x + b.y + b.z + b.w;
        float sq = a.x*a.x + a.y*a.y + a.z*a.z + a.w*a.w
                 + b.x*b.x + b.y*b.y + b.z*b.z + b.w*b.w;
        #pragma unroll
        for (int o = 16; o > 0; o >>= 1) {
            s  += __shfl_xor_sync(0xffffffffu, s,  o);
            sq += __shfl_xor_sync(0xffffffffu, sq, o);
        }
        float mu   = s * (1.f / 256.f);
        float var  = sq * (1.f / 256.f) - mu * mu;
        float rsig = rsqrtf(var + LN_EPS);

        int gnode = node0 + n;
        if (gnode < NODES) {
            float4 o1, o2;
            o1.x = (a.x - mu) * rsig * g1.x + e1.x;
            o1.y = (a.y - mu) * rsig * g1.y + e1.y;
            o1.z = (a.z - mu) * rsig * g1.z + e1.z;
            o1.w = (a.w - mu) * rsig * g1.w + e1.w;
            o2.x = (b.x - mu) * rsig * g2.x + e2.x;
            o2.y = (b.y - mu) * rsig * g2.y + e2.y;
            o2.z = (b.z - mu) * rsig * g2.z + e2.z;
            o2.w = (b.w - mu) * rsig * g2.w + e2.w;

            float4* og = reinterpret_cast<float4*>(out + (size_t)gnode * DO2);
            og[lane]      = o1;
            og[lane + 32] = o2;
        }
    }
}

// ---------------------------------------------------------------------------
extern "C" void kernel_launch(void* const* d_in, const int* in_sizes, int n_in,
                              void* d_out, int out_size) {
    const float* h        = (const float*)d_in[0];
    const int*   edge_row = (const int*)  d_in[1];
    const int*   edge_col = (const int*)  d_in[2];
    const float* edge_val = (const float*)d_in[3];
    const float* W_self   = (const float*)d_in[4];
    const float* b_self   = (const float*)d_in[5];
    const float* W_neigh  = (const float*)d_in[6];
    const float* b_neigh  = (const float*)d_in[7];
    const float* ln_gamma = (const float*)d_in[8];
    const float* ln_beta  = (const float*)d_in[9];
    float*       out      = (float*)d_out;

    const int E = in_sizes[1];

    // 1) zero support + build Wt
    {
        int n4 = NODES * D / 4;
        prep_kernel<<<(n4 + 255) / 256, 256>>>(W_self, W_neigh);
    }
    // 2) SpMM scatter: one warp per edge
    {
        long long threads = (long long)E * 32;
        int blocks = (int)((threads + 255) / 256);
        spmm_scatter_kernel<<<blocks, 256>>>(h, edge_row, edge_col, edge_val, E);
    }
    // 3) fused GEMM + ReLU + LayerNorm
    gemm_ln_kernel<<<(NODES + TILE - 1) / TILE, 256>>>(h, b_self, b_neigh,
                                                       ln_gamma, ln_beta, out);
}

// round 4
// speedup vs baseline: 1.2813x; 1.2813x over previous
#include <cuda_runtime.h>

#define D      128
#define DO2    256          // 2*D_OUT
#define NODES  50000
#define E_MAX  800000
#define TILE   32           // nodes per block in gemm_ln
#define LN_EPS 1e-5f
#define SCAN_BLOCKS ((NODES + 255) / 256)   // 196

// Scratch (no cudaMalloc allowed)
__device__ float g_support[NODES * D];   // 25.6 MB
__device__ float g_Wt[D * DO2];
__device__ int   g_cnt[NODES];           // degree per row
__device__ int   g_ptr[NODES];           // exclusive offsets -> end offsets after scatter
__device__ int   g_bsum[256];
__device__ int   g_boff[256];
__device__ int2  g_ecv[E_MAX];           // CSR-ordered (col, val_bits)

// ---------------------------------------------------------------------------
// prep: build transposed weight matrix + zero degree counters
__global__ void prep_kernel(const float* __restrict__ Ws,
                            const float* __restrict__ Wn) {
    int i = blockIdx.x * blockDim.x + threadIdx.x;
    if (i < NODES) g_cnt[i] = 0;
    if (i < D * DO2) {
        int k = i / DO2;
        int c = i % DO2;
        g_Wt[i] = (c < D) ? Ws[c * D + k] : Wn[(c - D) * D + k];
    }
}

// ---------------------------------------------------------------------------
__global__ void hist_kernel(const int* __restrict__ row, int E) {
    int e = blockIdx.x * blockDim.x + threadIdx.x;
    if (e < E) atomicAdd(&g_cnt[row[e]], 1);
}

// Block-level inclusive scan (Hillis-Steele), 256 wide
__device__ __forceinline__ int block_scan_incl(int v, int t, int* s) {
    s[t] = v;
    __syncthreads();
    #pragma unroll
    for (int o = 1; o < 256; o <<= 1) {
        int add = (t >= o) ? s[t - o] : 0;
        __syncthreads();
        s[t] += add;
        __syncthreads();
    }
    return s[t];
}

__global__ void scan1_kernel() {
    __shared__ int s[256];
    int t = threadIdx.x;
    int i = blockIdx.x * 256 + t;
    int v = (i < NODES) ? g_cnt[i] : 0;
    int incl = block_scan_incl(v, t, s);
    if (i < NODES) g_ptr[i] = incl - v;
    if (t == 255) g_bsum[blockIdx.x] = incl;
}

__global__ void scan2_kernel() {
    __shared__ int s[256];
    int t = threadIdx.x;
    int v = (t < SCAN_BLOCKS) ? g_bsum[t] : 0;
    int incl = block_scan_incl(v, t, s);
    g_boff[t] = incl - v;
}

__global__ void scan3_kernel() {
    int i = blockIdx.x * blockDim.x + threadIdx.x;
    if (i < NODES) g_ptr[i] += g_boff[i >> 8];
}

// Bucket-scatter edges into CSR order; g_ptr[r] becomes row-end offset.
__global__ void scatter_kernel(const int*  __restrict__ row,
                               const int*  __restrict__ col,
                               const float* __restrict__ val,
                               int E) {
    int e = blockIdx.x * blockDim.x + threadIdx.x;
    if (e >= E) return;
    int r = row[e];
    int p = atomicAdd(&g_ptr[r], 1);
    g_ecv[p] = make_int2(col[e], __float_as_int(val[e]));
}

// ---------------------------------------------------------------------------
// CSR SpMM: one warp per destination row, lane = 4 features, register acc.
__global__ __launch_bounds__(256)
void spmm_csr_kernel(const float* __restrict__ h) {
    int gw   = (blockIdx.x * blockDim.x + threadIdx.x) >> 5;
    int lane = threadIdx.x & 31;
    if (gw >= NODES) return;

    int end = g_ptr[gw];
    int beg = end - g_cnt[gw];

    float4 acc = make_float4(0.f, 0.f, 0.f, 0.f);

    int  e  = beg;
    int2 cv = (e < end) ? __ldg(&g_ecv[e]) : make_int2(0, 0);
    while (e < end) {
        int2 cur = cv;
        if (e + 1 < end) cv = __ldg(&g_ecv[e + 1]);   // prefetch next edge
        float  v = __int_as_float(cur.y);
        float4 x = __ldg(reinterpret_cast<const float4*>(h + (size_t)cur.x * D) + lane);
        acc.x = fmaf(v, x.x, acc.x);
        acc.y = fmaf(v, x.y, acc.y);
        acc.z = fmaf(v, x.z, acc.z);
        acc.w = fmaf(v, x.w, acc.w);
        e++;
    }
    reinterpret_cast<float4*>(g_support + (size_t)gw * D)[lane] = acc;
}

// ---------------------------------------------------------------------------
// Fused GEMM + concat + ReLU + LayerNorm (round-2 scalar version — measured best).
__global__ __launch_bounds__(256)
void gemm_ln_kernel(const float* __restrict__ h,
                    const float* __restrict__ b_self,
                    const float* __restrict__ b_neigh,
                    const float* __restrict__ gamma,
                    const float* __restrict__ beta,
                    float* __restrict__ out) {
    __shared__ float smem[TILE * DO2];
    float* sH = smem;
    float* sS = smem + TILE * D;

    const int tid   = threadIdx.x;
    const int node0 = blockIdx.x * TILE;

    for (int i = tid; i < TILE * (D / 4); i += 256) {
        int row   = i >> 5;
        int gnode = node0 + row;
        float4 a = make_float4(0.f, 0.f, 0.f, 0.f);
        float4 s = a;
        if (gnode < NODES) {
            a = reinterpret_cast<const float4*>(h + (size_t)gnode * D)[i & 31];
            s = reinterpret_cast<const float4*>(g_support + (size_t)gnode * D)[i & 31];
        }
        reinterpret_cast<float4*>(sH)[i] = a;
        reinterpret_cast<float4*>(sS)[i] = s;
    }
    __syncthreads();

    const int  cq    = tid & 63;
    const int  ng    = tid >> 6;
    const int  n0    = ng * 8;
    const bool neigh = (cq >= 32);
    const float* sX  = neigh ? sS : sH;

    float4 bias = neigh ? reinterpret_cast<const float4*>(b_neigh)[cq - 32]
                        : reinterpret_cast<const float4*>(b_self)[cq];

    float acc[8][4];
    #pragma unroll
    for (int j = 0; j < 8; j++) {
        acc[j][0] = bias.x; acc[j][1] = bias.y; acc[j][2] = bias.z; acc[j][3] = bias.w;
    }

    const float4* Wt4 = reinterpret_cast<const float4*>(g_Wt);
    #pragma unroll 2
    for (int k = 0; k < D; k += 4) {
        float4 w0 = __ldg(Wt4 + (k + 0) * 64 + cq);
        float4 w1 = __ldg(Wt4 + (k + 1) * 64 + cq);
        float4 w2 = __ldg(Wt4 + (k + 2) * 64 + cq);
        float4 w3 = __ldg(Wt4 + (k + 3) * 64 + cq);
        #pragma unroll
        for (int j = 0; j < 8; j++) {
            float4 xv = *reinterpret_cast<const float4*>(sX + (n0 + j) * D + k);
            acc[j][0] = fmaf(w0.x, xv.x, acc[j][0]);
            acc[j][1] = fmaf(w0.y, xv.x, acc[j][1]);
            acc[j][2] = fmaf(w0.z, xv.x, acc[j][2]);
            acc[j][3] = fmaf(w0.w, xv.x, acc[j][3]);
            acc[j][0] = fmaf(w1.x, xv.y, acc[j][0]);
            acc[j][1] = fmaf(w1.y, xv.y, acc[j][1]);
            acc[j][2] = fmaf(w1.z, xv.y, acc[j][2]);
            acc[j][3] = fmaf(w1.w, xv.y, acc[j][3]);
            acc[j][0] = fmaf(w2.x, xv.z, acc[j][0]);
            acc[j][1] = fmaf(w2.y, xv.z, acc[j][1]);
            acc[j][2] = fmaf(w2.z, xv.z, acc[j][2]);
            acc[j][3] = fmaf(w2.w, xv.z, acc[j][3]);
            acc[j][0] = fmaf(w3.x, xv.w, acc[j][0]);
            acc[j][1] = fmaf(w3.y, xv.w, acc[j][1]);
            acc[j][2] = fmaf(w3.z, xv.w, acc[j][2]);
            acc[j][3] = fmaf(w3.w, xv.w, acc[j][3]);
        }
    }
    __syncthreads();

    #pragma unroll
    for (int j = 0; j < 8; j++) {
        float4 r;
        r.x = fmaxf(acc[j][0], 0.f);
        r.y = fmaxf(acc[j][1], 0.f);
        r.z = fmaxf(acc[j][2], 0.f);
        r.w = fmaxf(acc[j][3], 0.f);
        reinterpret_cast<float4*>(smem)[(n0 + j) * 64 + cq] = r;
    }
    __syncthreads();

    const int wid  = tid >> 5;
    const int lane = tid & 31;

    float4 g1 = __ldg(reinterpret_cast<const float4*>(gamma) + lane);
    float4 g2 = __ldg(reinterpret_cast<const float4*>(gamma) + lane + 32);
    float4 e1 = __ldg(reinterpret_cast<const float4*>(beta)  + lane);
    float4 e2 = __ldg(reinterpret_cast<const float4*>(beta)  + lane + 32);

    #pragma unroll
    for (int rr = 0; rr < 4; rr++) {
        int n = wid * 4 + rr;
        float4 a = reinterpret_cast<float4*>(smem)[n * 64 + lane];
        float4 b = reinterpret_cast<float4*>(smem)[n * 64 + lane + 32];
        float s  = a.x + a.y + a.z + a.w + b.x + b.y + b.z + b.w;
        float sq = a.x*a.x + a.y*a.y + a.z*a.z + a.w*a.w
                 + b.x*b.x + b.y*b.y + b.z*b.z + b.w*b.w;
        #pragma unroll
        for (int o = 16; o > 0; o >>= 1) {
            s  += __shfl_xor_sync(0xffffffffu, s,  o);
            sq += __shfl_xor_sync(0xffffffffu, sq, o);
        }
        float mu   = s * (1.f / 256.f);
        float var  = sq * (1.f / 256.f) - mu * mu;
        float rsig = rsqrtf(var + LN_EPS);

        int gnode = node0 + n;
        if (gnode < NODES) {
            float4 o1, o2;
            o1.x = (a.x - mu) * rsig * g1.x + e1.x;
            o1.y = (a.y - mu) * rsig * g1.y + e1.y;
            o1.z = (a.z - mu) * rsig * g1.z + e1.z;
            o1.w = (a.w - mu) * rsig * g1.w + e1.w;
            o2.x = (b.x - mu) * rsig * g2.x + e2.x;
            o2.y = (b.y - mu) * rsig * g2.y + e2.y;
            o2.z = (b.z - mu) * rsig * g2.z + e2.z;
            o2.w = (b.w - mu) * rsig * g2.w + e2.w;

            float4* og = reinterpret_cast<float4*>(out + (size_t)gnode * DO2);
            og[lane]      = o1;
            og[lane + 32] = o2;
        }
    }
}

// ---------------------------------------------------------------------------
extern "C" void kernel_launch(void* const* d_in, const int* in_sizes, int n_in,
                              void* d_out, int out_size) {
    const float* h        = (const float*)d_in[0];
    const int*   edge_row = (const int*)  d_in[1];
    const int*   edge_col = (const int*)  d_in[2];
    const float* edge_val = (const float*)d_in[3];
    const float* W_self   = (const float*)d_in[4];
    const float* b_self   = (const float*)d_in[5];
    const float* W_neigh  = (const float*)d_in[6];
    const float* b_neigh  = (const float*)d_in[7];
    const float* ln_gamma = (const float*)d_in[8];
    const float* ln_beta  = (const float*)d_in[9];
    float*       out      = (float*)d_out;

    const int E = in_sizes[1];
    const int eb = (E + 255) / 256;

    prep_kernel<<<SCAN_BLOCKS, 256>>>(W_self, W_neigh);
    hist_kernel<<<eb, 256>>>(edge_row, E);
    scan1_kernel<<<SCAN_BLOCKS, 256>>>();
    scan2_kernel<<<1, 256>>>();
    scan3_kernel<<<SCAN_BLOCKS, 256>>>();
    scatter_kernel<<<eb, 256>>>(edge_row, edge_col, edge_val, E);
    spmm_csr_kernel<<<(NODES * 32 + 255) / 256, 256>>>(h);
    gemm_ln_kernel<<<(NODES + TILE - 1) / TILE, 256>>>(h, b_self, b_neigh,
                                                       ln_gamma, ln_beta, out);
}

// round 7
// speedup vs baseline: 1.5119x; 1.1800x over previous
#include <cuda_runtime.h>
#include <cuda_bf16.h>
#include <cstdint>

#define D      128
#define DO2    256
#define NODES  50000
#define E_MAX  800000
#define LN_EPS 1e-5f
#define SCAN_BLOCKS ((NODES + 255) / 256)   // 196

#define MTILE  64
#define GRID_G ((NODES + MTILE - 1) / MTILE) // 782

// X tile in smem: 4 sub-tiles [half(h/support)][part(hi/lo)], each 64 rows x 68 words
#define XROW_W 68                       // words per row (136 bf16; data in first 64)
#define XTILE_W (64 * XROW_W)           // 4352 words
#define SMEM_GEMM (4 * XTILE_W * 4)     // 69632 bytes

#define NKS    8                        // k-steps: D / 16
#define WFRAG_N (2 * 32 * NKS * 2 * 32) // 32768 words

// Scratch
__device__ float    g_support[NODES * D];
__device__ int      g_cnt[NODES];
__device__ int      g_ptr[NODES];
__device__ int      g_bsum[256];
__device__ int2     g_ecv[E_MAX];
// W fragments: [p hi/lo][ntile 0..31][kstep 0..7][reg 0..1][lane 0..31]
__device__ uint32_t g_Wfrag[WFRAG_N];

// ---------------------------------------------------------------------------
__device__ __forceinline__ uint32_t pack_bf2(__nv_bfloat16 lo, __nv_bfloat16 hi) {
    return (uint32_t)__bfloat16_as_ushort(hi) << 16 | (uint32_t)__bfloat16_as_ushort(lo);
}

__device__ __forceinline__ void mma_bf16(float& d0, float& d1, float& d2, float& d3,
                                         uint32_t a0, uint32_t a1, uint32_t a2, uint32_t a3,
                                         uint32_t b0, uint32_t b1) {
    asm volatile(
        "mma.sync.aligned.m16n8k16.row.col.f32.bf16.bf16.f32 "
        "{%0,%1,%2,%3}, {%4,%5,%6,%7}, {%8,%9}, {%0,%1,%2,%3};"
        : "+f"(d0), "+f"(d1), "+f"(d2), "+f"(d3)
        : "r"(a0), "r"(a1), "r"(a2), "r"(a3), "r"(b0), "r"(b1));
}

// ---------------------------------------------------------------------------
// prep: zero degree counters + build bf16-split W fragments
// flat idx: lane(5) | reg(1) | ks(3) | nt(5) | p(1)   -> 32768 entries
__global__ void prep_kernel(const float* __restrict__ Ws,
                            const float* __restrict__ Wn) {
    int idx = blockIdx.x * blockDim.x + threadIdx.x;
    if (idx < NODES) g_cnt[idx] = 0;
    if (idx < WFRAG_N) {
        int lane = idx & 31;
        int reg  = (idx >> 5) & 1;
        int ks   = (idx >> 6) & 7;
        int nt   = (idx >> 9) & 31;
        int p    = idx >> 14;
        int n    = nt * 8 + (lane >> 2);
        int k    = ks * 16 + reg * 8 + 2 * (lane & 3);
        const float* W = (nt < 16) ? Ws : Wn;
        int nn = (nt < 16) ? n : (n - 128);
        float w0 = W[nn * D + k];
        float w1 = W[nn * D + k + 1];
        __nv_bfloat16 h0 = __float2bfloat16_rn(w0);
        __nv_bfloat16 h1 = __float2bfloat16_rn(w1);
        __nv_bfloat16 v0, v1;
        if (p == 0) { v0 = h0; v1 = h1; }
        else {
            v0 = __float2bfloat16_rn(w0 - __bfloat162float(h0));
            v1 = __float2bfloat16_rn(w1 - __bfloat162float(h1));
        }
        g_Wfrag[idx] = pack_bf2(v0, v1);
    }
}

// ---------------------------------------------------------------------------
__global__ void hist_kernel(const int* __restrict__ row, int E) {
    int e = blockIdx.x * blockDim.x + threadIdx.x;
    if (e < E) atomicAdd(&g_cnt[row[e]], 1);
}

__device__ __forceinline__ int block_scan_incl(int v, int t, int* s) {
    s[t] = v;
    __syncthreads();
    #pragma unroll
    for (int o = 1; o < 256; o <<= 1) {
        int add = (t >= o) ? s[t - o] : 0;
        __syncthreads();
        s[t] += add;
        __syncthreads();
    }
    return s[t];
}

__global__ void scan1_kernel() {
    __shared__ int s[256];
    int t = threadIdx.x;
    int i = blockIdx.x * 256 + t;
    int v = (i < NODES) ? g_cnt[i] : 0;
    int incl = block_scan_incl(v, t, s);
    if (i < NODES) g_ptr[i] = incl - v;
    if (t == 255) g_bsum[blockIdx.x] = incl;
}

// merged: re-scan block sums locally + apply offset
__global__ void scan3_kernel() {
    __shared__ int s[256];
    int t = threadIdx.x;
    int v = (t < SCAN_BLOCKS) ? g_bsum[t] : 0;
    block_scan_incl(v, t, s);
    int b   = blockIdx.x;
    int off = (b == 0) ? 0 : s[b - 1];
    int i = b * 256 + t;
    if (i < NODES) g_ptr[i] += off;
}

__global__ void scatter_kernel(const int*  __restrict__ row,
                               const int*  __restrict__ col,
                               const float* __restrict__ val,
                               int E) {
    int e = blockIdx.x * blockDim.x + threadIdx.x;
    if (e >= E) return;
    int r = row[e];
    int p = atomicAdd(&g_ptr[r], 1);
    g_ecv[p] = make_int2(col[e], __float_as_int(val[e]));
}

// ---------------------------------------------------------------------------
__global__ __launch_bounds__(256)
void spmm_csr_kernel(const float* __restrict__ h) {
    int gw   = (blockIdx.x * blockDim.x + threadIdx.x) >> 5;
    int lane = threadIdx.x & 31;
    if (gw >= NODES) return;

    int end = g_ptr[gw];
    int beg = end - g_cnt[gw];

    float4 acc = make_float4(0.f, 0.f, 0.f, 0.f);
    int  e  = beg;
    int2 cv = (e < end) ? __ldg(&g_ecv[e]) : make_int2(0, 0);
    while (e < end) {
        int2 cur = cv;
        if (e + 1 < end) cv = __ldg(&g_ecv[e + 1]);
        float  v = __int_as_float(cur.y);
        float4 x = __ldg(reinterpret_cast<const float4*>(h + (size_t)cur.x * D) + lane);
        acc.x = fmaf(v, x.x, acc.x);
        acc.y = fmaf(v, x.y, acc.y);
        acc.z = fmaf(v, x.z, acc.z);
        acc.w = fmaf(v, x.w, acc.w);
        e++;
    }
    reinterpret_cast<float4*>(g_support + (size_t)gw * D)[lane] = acc;
}

// ---------------------------------------------------------------------------
// Tensor-core fused GEMM (bf16x3 split via mma.sync) + concat + ReLU + LN.
// 256 threads, 64 nodes/CTA. Warp w: half = w>>2 (0:self/h, 1:neigh/support),
// rows mr = (w&3)*16 .. +16, cols = its half's 128 channels.
__global__ __launch_bounds__(256)
void gemm_ln_tc_kernel(const float* __restrict__ h,
                       const float* __restrict__ b_self,
                       const float* __restrict__ b_neigh,
                       const float* __restrict__ gamma,
                       const float* __restrict__ beta,
                       float* __restrict__ out) {
    extern __shared__ uint32_t sX[];        // [half*2+part][64][68] words
    __shared__ float sSum[2][64];
    __shared__ float sSq[2][64];

    const int tid   = threadIdx.x;
    const int node0 = blockIdx.x * MTILE;

    // Stage X: convert fp32 rows -> bf16 hi/lo tiles (row stride 68 words)
    for (int i = tid; i < 64 * 32; i += 256) {
        int row = i >> 5;           // 0..63
        int q4  = i & 31;           // float4 index, k = 4*q4
        int gn  = node0 + row;
        #pragma unroll
        for (int half = 0; half < 2; half++) {
            const float* src = half ? g_support : h;
            float4 x = (gn < NODES)
                     ? __ldg(reinterpret_cast<const float4*>(src + (size_t)gn * D) + q4)
                     : make_float4(0.f, 0.f, 0.f, 0.f);
            __nv_bfloat16 hx = __float2bfloat16_rn(x.x);
            __nv_bfloat16 hy = __float2bfloat16_rn(x.y);
            __nv_bfloat16 hz = __float2bfloat16_rn(x.z);
            __nv_bfloat16 hw = __float2bfloat16_rn(x.w);
            __nv_bfloat16 lx = __float2bfloat16_rn(x.x - __bfloat162float(hx));
            __nv_bfloat16 ly = __float2bfloat16_rn(x.y - __bfloat162float(hy));
            __nv_bfloat16 lz = __float2bfloat16_rn(x.z - __bfloat162float(hz));
            __nv_bfloat16 lw = __float2bfloat16_rn(x.w - __bfloat162float(hw));
            uint32_t* tHi = sX + (half * 2 + 0) * XTILE_W + row * XROW_W;
            uint32_t* tLo = sX + (half * 2 + 1) * XTILE_W + row * XROW_W;
            tHi[2 * q4]     = pack_bf2(hx, hy);
            tHi[2 * q4 + 1] = pack_bf2(hz, hw);
            tLo[2 * q4]     = pack_bf2(lx, ly);
            tLo[2 * q4 + 1] = pack_bf2(lz, lw);
        }
    }
    __syncthreads();

    const int wid  = tid >> 5;
    const int lane = tid & 31;
    const int half = wid >> 2;
    const int mr   = (wid & 3) * 16;
    const int gr   = lane >> 2;     // 0..7
    const int q    = lane & 3;      // 0..3

    float acc[16][4];
    #pragma unroll
    for (int nt = 0; nt < 16; nt++)
        acc[nt][0] = acc[nt][1] = acc[nt][2] = acc[nt][3] = 0.f;

    // A-frag smem base (conflict-free: bank = 4*gr + q + 8*ks mod 32)
    const uint32_t* aHi = sX + (half * 2 + 0) * XTILE_W + (mr + gr) * XROW_W + q;
    const uint32_t* aLo = sX + (half * 2 + 1) * XTILE_W + (mr + gr) * XROW_W + q;
    // B-frag global: flat = ((p*32 + gnt)*NKS + ks)*64 + reg*32 + lane
    const uint32_t* bBase = g_Wfrag + (half * 16) * (NKS * 64) + lane;

    #pragma unroll
    for (int ks = 0; ks < NKS; ks++) {
        const int ko = ks * 8;
        uint32_t a0h = aHi[ko],     a1h = aHi[ko + 8 * XROW_W];
        uint32_t a2h = aHi[ko + 4], a3h = aHi[ko + 4 + 8 * XROW_W];
        uint32_t a0l = aLo[ko],     a1l = aLo[ko + 8 * XROW_W];
        uint32_t a2l = aLo[ko + 4], a3l = aLo[ko + 4 + 8 * XROW_W];
        const uint32_t* bp = bBase + ks * 64;
        #pragma unroll
        for (int nt = 0; nt < 16; nt++) {
            const uint32_t* bq = bp + nt * (NKS * 64);
            uint32_t b0h = __ldg(bq);
            uint32_t b1h = __ldg(bq + 32);
            uint32_t b0l = __ldg(bq + 32 * NKS * 64);        // p=1 offset: 16384
            uint32_t b1l = __ldg(bq + 32 * NKS * 64 + 32);
            mma_bf16(acc[nt][0], acc[nt][1], acc[nt][2], acc[nt][3],
                     a0h, a1h, a2h, a3h, b0h, b1h);
            mma_bf16(acc[nt][0], acc[nt][1], acc[nt][2], acc[nt][3],
                     a0h, a1h, a2h, a3h, b0l, b1l);
            mma_bf16(acc[nt][0], acc[nt][1], acc[nt][2], acc[nt][3],
                     a0l, a1l, a2l, a3l, b0h, b1h);
        }
    }

    // Epilogue: bias + ReLU, row partial stats
    const float2* bb = reinterpret_cast<const float2*>(half ? b_neigh : b_self);
    float sA = 0.f, qA = 0.f, sB = 0.f, qB = 0.f;
    #pragma unroll
    for (int nt = 0; nt < 16; nt++) {
        float2 bv = __ldg(bb + nt * 4 + q);
        float v0 = fmaxf(acc[nt][0] + bv.x, 0.f);
        float v1 = fmaxf(acc[nt][1] + bv.y, 0.f);
        float v2 = fmaxf(acc[nt][2] + bv.x, 0.f);
        float v3 = fmaxf(acc[nt][3] + bv.y, 0.f);
        acc[nt][0] = v0; acc[nt][1] = v1; acc[nt][2] = v2; acc[nt][3] = v3;
        sA += v0 + v1;  qA += v0 * v0 + v1 * v1;
        sB += v2 + v3;  qB += v2 * v2 + v3 * v3;
    }
    #pragma unroll
    for (int o = 1; o <= 2; o <<= 1) {
        sA += __shfl_xor_sync(0xffffffffu, sA, o);
        qA += __shfl_xor_sync(0xffffffffu, qA, o);
        sB += __shfl_xor_sync(0xffffffffu, sB, o);
        qB += __shfl_xor_sync(0xffffffffu, qB, o);
    }
    if (q == 0) {
        sSum[half][mr + gr]     = sA;  sSq[half][mr + gr]     = qA;
        sSum[half][mr + gr + 8] = sB;  sSq[half][mr + gr + 8] = qB;
    }
    __syncthreads();

    int rowA = mr + gr, rowB = mr + gr + 8;
    float muA = (sSum[0][rowA] + sSum[1][rowA]) * (1.f / 256.f);
    float vaA = (sSq[0][rowA] + sSq[1][rowA]) * (1.f / 256.f) - muA * muA;
    float rsA = rsqrtf(vaA + LN_EPS);
    float muB = (sSum[0][rowB] + sSum[1][rowB]) * (1.f / 256.f);
    float vaB = (sSq[0][rowB] + sSq[1][rowB]) * (1.f / 256.f) - muB * muB;
    float rsB = rsqrtf(vaB + LN_EPS);

    const float2* gg = reinterpret_cast<const float2*>(gamma) + half * 64;
    const float2* ee = reinterpret_cast<const float2*>(beta)  + half * 64;
    int gnA = node0 + rowA;
    int gnB = node0 + rowB;
    #pragma unroll
    for (int nt = 0; nt < 16; nt++) {
        float2 gv = __ldg(gg + nt * 4 + q);
        float2 ev = __ldg(ee + nt * 4 + q);
        int coff = half * 128 + nt * 8 + 2 * q;
        if (gnA < NODES) {
            float2 o;
            o.x = (acc[nt][0] - muA) * rsA * gv.x + ev.x;
            o.y = (acc[nt][1] - muA) * rsA * gv.y + ev.y;
            *reinterpret_cast<float2*>(out + (size_t)gnA * DO2 + coff) = o;
        }
        if (gnB < NODES) {
            float2 o;
            o.x = (acc[nt][2] - muB) * rsB * gv.x + ev.x;
            o.y = (acc[nt][3] - muB) * rsB * gv.y + ev.y;
            *reinterpret_cast<float2*>(out + (size_t)gnB * DO2 + coff) = o;
        }
    }
}

// ---------------------------------------------------------------------------
extern "C" void kernel_launch(void* const* d_in, const int* in_sizes, int n_in,
                              void* d_out, int out_size) {
    const float* h        = (const float*)d_in[0];
    const int*   edge_row = (const int*)  d_in[1];
    const int*   edge_col = (const int*)  d_in[2];
    const float* edge_val = (const float*)d_in[3];
    const float* W_self   = (const float*)d_in[4];
    const float* b_self   = (const float*)d_in[5];
    const float* W_neigh  = (const float*)d_in[6];
    const float* b_neigh  = (const float*)d_in[7];
    const float* ln_gamma = (const float*)d_in[8];
    const float* ln_beta  = (const float*)d_in[9];
    float*       out      = (float*)d_out;

    const int E  = in_sizes[1];
    const int eb = (E + 255) / 256;

    static bool attr_done = false;
    if (!attr_done) {
        cudaFuncSetAttribute(gemm_ln_tc_kernel,
                             cudaFuncAttributeMaxDynamicSharedMemorySize, SMEM_GEMM);
        attr_done = true;
    }

    prep_kernel<<<256, 256>>>(W_self, W_neigh);
    hist_kernel<<<eb, 256>>>(edge_row, E);
    scan1_kernel<<<SCAN_BLOCKS, 256>>>();
    scan3_kernel<<<SCAN_BLOCKS, 256>>>();
    scatter_kernel<<<eb, 256>>>(edge_row, edge_col, edge_val, E);
    spmm_csr_kernel<<<(NODES * 32 + 255) / 256, 256>>>(h);
    gemm_ln_tc_kernel<<<GRID_G, 256, SMEM_GEMM>>>(h, b_self, b_neigh,
                                                  ln_gamma, ln_beta, out);
}

// round 8
// speedup vs baseline: 1.7329x; 1.1461x over previous
#include <cuda_runtime.h>
#include <cuda_bf16.h>
#include <cstdint>

#define D      128
#define DO2    256
#define NODES  50000
#define E_MAX  800000
#define LN_EPS 1e-5f

#define CAP    64                      // bucket capacity per row (mean deg 16)
#define SPILL_MAX 8192

#define MTILE  64
#define GRID_G ((NODES + MTILE - 1) / MTILE) // 782

// X tile in smem: 4 sub-tiles [half(h/support)][part(hi/lo)], each 64 rows x 68 words
#define XROW_W 68
#define XTILE_W (64 * XROW_W)
#define SMEM_GEMM (4 * XTILE_W * 4)     // 69632 bytes

#define NKS    8                        // k-steps: D / 16

// Scratch
__device__ float    g_support[NODES * D];
__device__ int      g_cnt[NODES];
__device__ int2     g_slots[NODES * CAP];   // 25.6 MB bucketed edges (col, val_bits)
__device__ int4     g_spill[SPILL_MAX];     // (row, col, val_bits, -)
__device__ int      g_nspill;
// W fragments, LDG.128-packed: uint4[half][nt(16)][ks(8)][lane(32)]
// .x=b0_hi .y=b1_hi .z=b0_lo .w=b1_lo
__device__ uint4    g_Wfrag[2 * 16 * NKS * 32];

// ---------------------------------------------------------------------------
__device__ __forceinline__ uint32_t pack_bf2(__nv_bfloat16 lo, __nv_bfloat16 hi) {
    return (uint32_t)__bfloat16_as_ushort(hi) << 16 | (uint32_t)__bfloat16_as_ushort(lo);
}

__device__ __forceinline__ void mma_bf16(float& d0, float& d1, float& d2, float& d3,
                                         uint32_t a0, uint32_t a1, uint32_t a2, uint32_t a3,
                                         uint32_t b0, uint32_t b1) {
    asm volatile(
        "mma.sync.aligned.m16n8k16.row.col.f32.bf16.bf16.f32 "
        "{%0,%1,%2,%3}, {%4,%5,%6,%7}, {%8,%9}, {%0,%1,%2,%3};"
        : "+f"(d0), "+f"(d1), "+f"(d2), "+f"(d3)
        : "r"(a0), "r"(a1), "r"(a2), "r"(a3), "r"(b0), "r"(b1));
}

// ---------------------------------------------------------------------------
// prep: zero counters + build packed bf16-split W fragments.
// word idx: w(2) | lane(5) | ks(3) | nt(4) | half(1)  -> 32768 words
__global__ void prep_kernel(const float* __restrict__ Ws,
                            const float* __restrict__ Wn) {
    int idx = blockIdx.x * blockDim.x + threadIdx.x;
    if (idx < NODES) g_cnt[idx] = 0;
    if (idx == 0) g_nspill = 0;
    if (idx < 2 * 16 * NKS * 32 * 4) {
        int w    = idx & 3;
        int lane = (idx >> 2) & 31;
        int ks   = (idx >> 7) & 7;
        int nt   = (idx >> 10) & 15;
        int half = (idx >> 14) & 1;
        int p    = w >> 1;
        int reg  = w & 1;
        int n    = nt * 8 + (lane >> 2);
        int k    = ks * 16 + reg * 8 + 2 * (lane & 3);
        const float* W = half ? Wn : Ws;
        float w0 = W[n * D + k];
        float w1 = W[n * D + k + 1];
        __nv_bfloat16 h0 = __float2bfloat16_rn(w0);
        __nv_bfloat16 h1 = __float2bfloat16_rn(w1);
        __nv_bfloat16 v0, v1;
        if (p == 0) { v0 = h0; v1 = h1; }
        else {
            v0 = __float2bfloat16_rn(w0 - __bfloat162float(h0));
            v1 = __float2bfloat16_rn(w1 - __bfloat162float(h1));
        }
        reinterpret_cast<uint32_t*>(g_Wfrag)[idx] = pack_bf2(v0, v1);
    }
}

// ---------------------------------------------------------------------------
// Bucket-scatter edges: fixed 64-slot buckets, overflow -> spill list.
__global__ void scatter_kernel(const int*  __restrict__ row,
                               const int*  __restrict__ col,
                               const float* __restrict__ val,
                               int E) {
    int e = blockIdx.x * blockDim.x + threadIdx.x;
    if (e >= E) return;
    int r = row[e];
    int slot = atomicAdd(&g_cnt[r], 1);
    if (slot < CAP) {
        g_slots[r * CAP + slot] = make_int2(col[e], __float_as_int(val[e]));
    } else {
        int sp = atomicAdd(&g_nspill, 1);
        if (sp < SPILL_MAX)
            g_spill[sp] = make_int4(r, col[e], __float_as_int(val[e]), 0);
    }
}

// ---------------------------------------------------------------------------
// Bucketed SpMM: one warp per row, lane = 4 features, register acc.
__global__ __launch_bounds__(256)
void spmm_csr_kernel(const float* __restrict__ h) {
    int gw   = (blockIdx.x * blockDim.x + threadIdx.x) >> 5;
    int lane = threadIdx.x & 31;
    if (gw >= NODES) return;

    int cnt = g_cnt[gw];
    if (cnt > CAP) cnt = CAP;
    int beg = gw * CAP;
    int end = beg + cnt;

    float4 acc = make_float4(0.f, 0.f, 0.f, 0.f);
    int  e  = beg;
    int2 cv = (e < end) ? __ldg(&g_slots[e]) : make_int2(0, 0);
    while (e < end) {
        int2 cur = cv;
        if (e + 1 < end) cv = __ldg(&g_slots[e + 1]);
        float  v = __int_as_float(cur.y);
        float4 x = __ldg(reinterpret_cast<const float4*>(h + (size_t)cur.x * D) + lane);
        acc.x = fmaf(v, x.x, acc.x);
        acc.y = fmaf(v, x.y, acc.y);
        acc.z = fmaf(v, x.z, acc.z);
        acc.w = fmaf(v, x.w, acc.w);
        e++;
    }
    reinterpret_cast<float4*>(g_support + (size_t)gw * D)[lane] = acc;
}

// Fold spilled edges into g_support (expected empty; runs after spmm).
__global__ void spill_fix_kernel(const float* __restrict__ h) {
    int nw   = (gridDim.x * blockDim.x) >> 5;
    int gw   = (blockIdx.x * blockDim.x + threadIdx.x) >> 5;
    int lane = threadIdx.x & 31;
    int n = g_nspill;
    if (n > SPILL_MAX) n = SPILL_MAX;
    for (int i = gw; i < n; i += nw) {
        int4 s = g_spill[i];
        float v = __int_as_float(s.z);
        float4 x = __ldg(reinterpret_cast<const float4*>(h + (size_t)s.y * D) + lane);
        x.x *= v; x.y *= v; x.z *= v; x.w *= v;
        atomicAdd(reinterpret_cast<float4*>(g_support + (size_t)s.x * D) + lane, x);
    }
}

// ---------------------------------------------------------------------------
// Tensor-core fused GEMM (bf16x3 split via mma.sync) + concat + ReLU + LN.
__global__ __launch_bounds__(256)
void gemm_ln_tc_kernel(const float* __restrict__ h,
                       const float* __restrict__ b_self,
                       const float* __restrict__ b_neigh,
                       const float* __restrict__ gamma,
                       const float* __restrict__ beta,
                       float* __restrict__ out) {
    extern __shared__ uint32_t sX[];        // [half*2+part][64][68] words
    __shared__ float sSum[2][64];
    __shared__ float sSq[2][64];

    const int tid   = threadIdx.x;
    const int node0 = blockIdx.x * MTILE;

    // Stage X: fp32 -> bf16 hi/lo tiles
    for (int i = tid; i < 64 * 32; i += 256) {
        int row = i >> 5;
        int q4  = i & 31;
        int gn  = node0 + row;
        #pragma unroll
        for (int half = 0; half < 2; half++) {
            const float* src = half ? g_support : h;
            float4 x = (gn < NODES)
                     ? __ldg(reinterpret_cast<const float4*>(src + (size_t)gn * D) + q4)
                     : make_float4(0.f, 0.f, 0.f, 0.f);
            __nv_bfloat16 hx = __float2bfloat16_rn(x.x);
            __nv_bfloat16 hy = __float2bfloat16_rn(x.y);
            __nv_bfloat16 hz = __float2bfloat16_rn(x.z);
            __nv_bfloat16 hw = __float2bfloat16_rn(x.w);
            __nv_bfloat16 lx = __float2bfloat16_rn(x.x - __bfloat162float(hx));
            __nv_bfloat16 ly = __float2bfloat16_rn(x.y - __bfloat162float(hy));
            __nv_bfloat16 lz = __float2bfloat16_rn(x.z - __bfloat162float(hz));
            __nv_bfloat16 lw = __float2bfloat16_rn(x.w - __bfloat162float(hw));
            uint32_t* tHi = sX + (half * 2 + 0) * XTILE_W + row * XROW_W;
            uint32_t* tLo = sX + (half * 2 + 1) * XTILE_W + row * XROW_W;
            tHi[2 * q4]     = pack_bf2(hx, hy);
            tHi[2 * q4 + 1] = pack_bf2(hz, hw);
            tLo[2 * q4]     = pack_bf2(lx, ly);
            tLo[2 * q4 + 1] = pack_bf2(lz, lw);
        }
    }
    __syncthreads();

    const int wid  = tid >> 5;
    const int lane = tid & 31;
    const int half = wid >> 2;
    const int mr   = (wid & 3) * 16;
    const int gr   = lane >> 2;
    const int q    = lane & 3;

    float acc[16][4];
    #pragma unroll
    for (int nt = 0; nt < 16; nt++)
        acc[nt][0] = acc[nt][1] = acc[nt][2] = acc[nt][3] = 0.f;

    const uint32_t* aHi = sX + (half * 2 + 0) * XTILE_W + (mr + gr) * XROW_W + q;
    const uint32_t* aLo = sX + (half * 2 + 1) * XTILE_W + (mr + gr) * XROW_W + q;
    const uint4* bBase = g_Wfrag + half * (16 * NKS * 32) + lane;

    #pragma unroll
    for (int ks = 0; ks < NKS; ks++) {
        const int ko = ks * 8;
        uint32_t a0h = aHi[ko],     a1h = aHi[ko + 8 * XROW_W];
        uint32_t a2h = aHi[ko + 4], a3h = aHi[ko + 4 + 8 * XROW_W];
        uint32_t a0l = aLo[ko],     a1l = aLo[ko + 8 * XROW_W];
        uint32_t a2l = aLo[ko + 4], a3l = aLo[ko + 4 + 8 * XROW_W];
        const uint4* bp = bBase + ks * 32;
        #pragma unroll
        for (int nt = 0; nt < 16; nt++) {
            uint4 b = __ldg(bp + nt * (NKS * 32));
            mma_bf16(acc[nt][0], acc[nt][1], acc[nt][2], acc[nt][3],
                     a0h, a1h, a2h, a3h, b.x, b.y);
            mma_bf16(acc[nt][0], acc[nt][1], acc[nt][2], acc[nt][3],
                     a0h, a1h, a2h, a3h, b.z, b.w);
            mma_bf16(acc[nt][0], acc[nt][1], acc[nt][2], acc[nt][3],
                     a0l, a1l, a2l, a3l, b.x, b.y);
        }
    }

    // Epilogue: bias + ReLU, row partial stats
    const float2* bb = reinterpret_cast<const float2*>(half ? b_neigh : b_self);
    float sA = 0.f, qA = 0.f, sB = 0.f, qB = 0.f;
    #pragma unroll
    for (int nt = 0; nt < 16; nt++) {
        float2 bv = __ldg(bb + nt * 4 + q);
        float v0 = fmaxf(acc[nt][0] + bv.x, 0.f);
        float v1 = fmaxf(acc[nt][1] + bv.y, 0.f);
        float v2 = fmaxf(acc[nt][2] + bv.x, 0.f);
        float v3 = fmaxf(acc[nt][3] + bv.y, 0.f);
        acc[nt][0] = v0; acc[nt][1] = v1; acc[nt][2] = v2; acc[nt][3] = v3;
        sA += v0 + v1;  qA += v0 * v0 + v1 * v1;
        sB += v2 + v3;  qB += v2 * v2 + v3 * v3;
    }
    #pragma unroll
    for (int o = 1; o <= 2; o <<= 1) {
        sA += __shfl_xor_sync(0xffffffffu, sA, o);
        qA += __shfl_xor_sync(0xffffffffu, qA, o);
        sB += __shfl_xor_sync(0xffffffffu, sB, o);
        qB += __shfl_xor_sync(0xffffffffu, qB, o);
    }
    if (q == 0) {
        sSum[half][mr + gr]     = sA;  sSq[half][mr + gr]     = qA;
        sSum[half][mr + gr + 8] = sB;  sSq[half][mr + gr + 8] = qB;
    }
    __syncthreads();

    int rowA = mr + gr, rowB = mr + gr + 8;
    float muA = (sSum[0][rowA] + sSum[1][rowA]) * (1.f / 256.f);
    float vaA = (sSq[0][rowA] + sSq[1][rowA]) * (1.f / 256.f) - muA * muA;
    float rsA = rsqrtf(vaA + LN_EPS);
    float muB = (sSum[0][rowB] + sSum[1][rowB]) * (1.f / 256.f);
    float vaB = (sSq[0][rowB] + sSq[1][rowB]) * (1.f / 256.f) - muB * muB;
    float rsB = rsqrtf(vaB + LN_EPS);

    const float2* gg = reinterpret_cast<const float2*>(gamma) + half * 64;
    const float2* ee = reinterpret_cast<const float2*>(beta)  + half * 64;
    int gnA = node0 + rowA;
    int gnB = node0 + rowB;
    #pragma unroll
    for (int nt = 0; nt < 16; nt++) {
        float2 gv = __ldg(gg + nt * 4 + q);
        float2 ev = __ldg(ee + nt * 4 + q);
        int coff = half * 128 + nt * 8 + 2 * q;
        if (gnA < NODES) {
            float2 o;
            o.x = (acc[nt][0] - muA) * rsA * gv.x + ev.x;
            o.y = (acc[nt][1] - muA) * rsA * gv.y + ev.y;
            *reinterpret_cast<float2*>(out + (size_t)gnA * DO2 + coff) = o;
        }
        if (gnB < NODES) {
            float2 o;
            o.x = (acc[nt][2] - muB) * rsB * gv.x + ev.x;
            o.y = (acc[nt][3] - muB) * rsB * gv.y + ev.y;
            *reinterpret_cast<float2*>(out + (size_t)gnB * DO2 + coff) = o;
        }
    }
}

// ---------------------------------------------------------------------------
extern "C" void kernel_launch(void* const* d_in, const int* in_sizes, int n_in,
                              void* d_out, int out_size) {
    const float* h        = (const float*)d_in[0];
    const int*   edge_row = (const int*)  d_in[1];
    const int*   edge_col = (const int*)  d_in[2];
    const float* edge_val = (const float*)d_in[3];
    const float* W_self   = (const float*)d_in[4];
    const float* b_self   = (const float*)d_in[5];
    const float* W_neigh  = (const float*)d_in[6];
    const float* b_neigh  = (const float*)d_in[7];
    const float* ln_gamma = (const float*)d_in[8];
    const float* ln_beta  = (const float*)d_in[9];
    float*       out      = (float*)d_out;

    const int E  = in_sizes[1];
    const int eb = (E + 255) / 256;

    static bool attr_done = false;
    if (!attr_done) {
        cudaFuncSetAttribute(gemm_ln_tc_kernel,
                             cudaFuncAttributeMaxDynamicSharedMemorySize, SMEM_GEMM);
        attr_done = true;
    }

    prep_kernel<<<256, 256>>>(W_self, W_neigh);
    scatter_kernel<<<eb, 256>>>(edge_row, edge_col, edge_val, E);
    spmm_csr_kernel<<<(NODES * 32 + 255) / 256, 256>>>(h);
    spill_fix_kernel<<<16, 256>>>(h);
    gemm_ln_tc_kernel<<<GRID_G, 256, SMEM_GEMM>>>(h, b_self, b_neigh,
                                                  ln_gamma, ln_beta, out);
}